// round 11
// baseline (speedup 1.0000x reference)
#include <cuda_runtime.h>
#include <cstdint>
#include <math.h>

#define BB 32
#define TT 128
#define VV 16000
#define EE 512
#define ZZ 128
#define HH 1024
#define RR 64   // 2*B rows: [0,32)=free-running (stream 0), [32,64)=teacher (stream 1)
#define START_ID 1
#define NSPLIT 8      // split-K for gate GEMMs
#define VC 4000       // vocab chunk per sample block (4 chunks/row)

// ---------------- device state ----------------
__device__ float g_h0[RR][HH];
__device__ float g_c0[RR][HH];
__device__ float g_h1[RR][HH];
__device__ float g_c1[RR][HH];
__device__ float g_part[NSPLIT][RR][4*HH];   // split-K partials for gate GEMMs
__device__ float g_logits[RR][VV];
__device__ float g_lpart[RR][VV];            // split-K partial for logits GEMM
__device__ float g_zb0[BB][4*HH];            // z @ Wx0[512:640] + b0 (step-invariant)
__device__ int   g_tok[RR];
// sampling partials (4 chunks per row)
__device__ float g_pm[RR][4];                // chunk max
__device__ float g_ps[RR][4];                // chunk sum of exp(L - chunk max)
__device__ float g_pb[RR][4];                // chunk best score (L + gumbel)
__device__ int   g_pi[RR][4];                // chunk best index

// ---------------- init ----------------
__global__ void init_kernel() {
    int i = blockIdx.x * blockDim.x + threadIdx.x;
    if (i < RR * HH) {
        ((float*)g_h0)[i] = 0.f;
        ((float*)g_c0)[i] = 0.f;
        ((float*)g_h1)[i] = 0.f;
        ((float*)g_c1)[i] = 0.f;
    }
    if (i < RR) g_tok[i] = START_ID;
}

// zb0[b][n] = sum_k z[b][k] * Wx0[512+k][n] + b0[n]   (once per launch)
__global__ void zb0_kernel(const float* __restrict__ z, const float* __restrict__ Wx0,
                           const float* __restrict__ b0) {
    int idx = blockIdx.x * blockDim.x + threadIdx.x;
    if (idx >= BB * 4 * HH) return;
    int b = idx >> 12, n = idx & 4095;
    float s = b0[n];
    for (int k = 0; k < ZZ; k++)
        s += z[b * ZZ + k] * Wx0[(size_t)(512 + k) * 4096 + n];
    g_zb0[b][n] = s;
}

// ---------------- threefry2x32 (exact JAX semantics) ----------------
__host__ __device__ __forceinline__ uint32_t rotl32(uint32_t v, int d) {
    return (v << d) | (v >> (32 - d));
}
__host__ __device__ __forceinline__ void threefry2x32(
    uint32_t k0, uint32_t k1, uint32_t x0, uint32_t x1, uint32_t* o0, uint32_t* o1)
{
    uint32_t ks2 = k0 ^ k1 ^ 0x1BD11BDAu;
    x0 += k0; x1 += k1;
#define TF_RND(R_) { x0 += x1; x1 = rotl32(x1, R_); x1 ^= x0; }
    TF_RND(13) TF_RND(15) TF_RND(26) TF_RND(6)
    x0 += k1;  x1 += ks2 + 1u;
    TF_RND(17) TF_RND(29) TF_RND(16) TF_RND(24)
    x0 += ks2; x1 += k0 + 2u;
    TF_RND(13) TF_RND(15) TF_RND(26) TF_RND(6)
    x0 += k0;  x1 += k1 + 3u;
    TF_RND(17) TF_RND(29) TF_RND(16) TF_RND(24)
    x0 += k1;  x1 += ks2 + 4u;
    TF_RND(13) TF_RND(15) TF_RND(26) TF_RND(6)
    x0 += ks2; x1 += k0 + 5u;
#undef TF_RND
    *o0 = x0; *o1 = x1;
}
static void h_fold(uint32_t k0, uint32_t k1, uint32_t d, uint32_t* o0, uint32_t* o1) {
    threefry2x32(k0, k1, 0u, d, o0, o1);
}
// JAX >= 0.4.30 partitionable threefry: counter = u64(idx) -> (0, idx), bits = o0^o1
__device__ __forceinline__ float jax_gumbel(uint32_t k0, uint32_t k1, uint32_t idx) {
    uint32_t o0, o1;
    threefry2x32(k0, k1, 0u, idx, &o0, &o1);
    uint32_t bits = o0 ^ o1;
    float f = __uint_as_float((bits >> 9) | 0x3f800000u) - 1.0f;
    float u = fmaxf(f, 1.17549435e-38f);
    return -logf(-logf(u));
}

// ---------------- GEMM: M=64, BN=128, Kc=16, 256 thr, 8x4/thread, dbuf smem ----
// MODE 0: gates L0, K=1536 (8 slices of 192), A=[emb[tok]|h0], B=[Wx0(0:512);Wh0]
// MODE 1: gates L1, K=2048 (8 slices of 256), A=[h0|h1],       B=[Wx1;Wh1]
// MODE 2: logits,   K=1024 (2 slices of 512), A=h1,            B=Wout (+bias on y0)
template<int MODE>
__device__ __forceinline__ void load_tile(
    int k0, int rA, int kkA, int n0, int tid,
    const float* __restrict__ emb,
    const float* __restrict__ W1,  const float* __restrict__ W2,
    const int* toks, float pa[4], float4& pb0, float4& pb1)
{
#pragma unroll
    for (int e = 0; e < 4; e++) {
        int k = k0 + kkA + e;
        float v;
        if (MODE == 0) {
            v = (k < 512) ? emb[(size_t)toks[rA] * EE + k] : g_h0[rA][k - 512];
        } else if (MODE == 1) {
            v = (k < 1024) ? g_h0[rA][k] : g_h1[rA][k - 1024];
        } else {
            v = g_h1[rA][k];
        }
        pa[e] = v;
    }
    {
        int kk = tid >> 4;
        int nn = (tid & 15) * 8;
        int k  = k0 + kk;
        const float* row;
        if (MODE == 0)      row = (k < 512)  ? (W1 + (size_t)k * 4096)
                                             : (W2 + (size_t)(k - 512) * 4096);
        else if (MODE == 1) row = (k < 1024) ? (W1 + (size_t)k * 4096)
                                             : (W2 + (size_t)(k - 1024) * 4096);
        else                row = W1 + (size_t)k * VV;
        pb0 = *reinterpret_cast<const float4*>(row + n0 + nn);
        pb1 = *reinterpret_cast<const float4*>(row + n0 + nn + 4);
    }
}

template<int MODE>
__global__ __launch_bounds__(256) void gemm_kernel(
    const float* __restrict__ emb,
    const float* __restrict__ W1,  const float* __restrict__ W2,
    const float* __restrict__ bias)
{
    constexpr int KTOT = (MODE == 0) ? 1536 : ((MODE == 1) ? 2048 : 1024);
    constexpr int KSL  = (MODE == 2) ? 2 : NSPLIT;
    constexpr int KS   = KTOT / KSL;     // 192 / 256 / 512

    __shared__ float As[2][16][64];
    __shared__ float Bs[2][16][128];
    __shared__ int   toks[64];

    const int tid = threadIdx.x;
    const int n0  = blockIdx.x * 128;
    const int ks0 = blockIdx.y * KS;
    const int tx  = tid & 31;
    const int ty  = tid >> 5;
    const int rA  = tid >> 2;
    const int kkA = (tid & 3) * 4;

    if (MODE == 0) {
        if (tid < 64) toks[tid] = g_tok[tid];
        __syncthreads();
    }

    float acc[8][4];
#pragma unroll
    for (int i = 0; i < 8; i++)
#pragma unroll
        for (int j = 0; j < 4; j++) acc[i][j] = 0.f;

    float pa[4]; float4 pb0, pb1;

    load_tile<MODE>(ks0, rA, kkA, n0, tid, emb, W1, W2, toks, pa, pb0, pb1);
    {
        int kk = tid >> 4, nn = (tid & 15) * 8;
#pragma unroll
        for (int e = 0; e < 4; e++) As[0][kkA + e][rA] = pa[e];
        *reinterpret_cast<float4*>(&Bs[0][kk][nn])     = pb0;
        *reinterpret_cast<float4*>(&Bs[0][kk][nn + 4]) = pb1;
    }
    __syncthreads();

    int buf = 0;
    for (int k0 = ks0; k0 < ks0 + KS; k0 += 16) {
        const bool more = (k0 + 16) < (ks0 + KS);
        if (more)
            load_tile<MODE>(k0 + 16, rA, kkA, n0, tid, emb, W1, W2, toks, pa, pb0, pb1);

#pragma unroll
        for (int kk = 0; kk < 16; kk++) {
            float4 a0 = *reinterpret_cast<const float4*>(&As[buf][kk][ty * 8]);
            float4 a1 = *reinterpret_cast<const float4*>(&As[buf][kk][ty * 8 + 4]);
            float4 b4 = *reinterpret_cast<const float4*>(&Bs[buf][kk][tx * 4]);
            float a[8] = {a0.x, a0.y, a0.z, a0.w, a1.x, a1.y, a1.z, a1.w};
#pragma unroll
            for (int i = 0; i < 8; i++) {
                acc[i][0] += a[i] * b4.x;
                acc[i][1] += a[i] * b4.y;
                acc[i][2] += a[i] * b4.z;
                acc[i][3] += a[i] * b4.w;
            }
        }

        if (more) {
            int kk = tid >> 4, nn = (tid & 15) * 8;
            int nb = buf ^ 1;
#pragma unroll
            for (int e = 0; e < 4; e++) As[nb][kkA + e][rA] = pa[e];
            *reinterpret_cast<float4*>(&Bs[nb][kk][nn])     = pb0;
            *reinterpret_cast<float4*>(&Bs[nb][kk][nn + 4]) = pb1;
        }
        __syncthreads();
        buf ^= 1;
    }

    // ---- epilogue ----
    const int nc = n0 + tx * 4;
    if (MODE == 2) {
        if (blockIdx.y == 0) {
            float4 bv = *reinterpret_cast<const float4*>(bias + nc);
#pragma unroll
            for (int i = 0; i < 8; i++) {
                int r = ty * 8 + i;
                float4 o;
                o.x = acc[i][0] + bv.x;
                o.y = acc[i][1] + bv.y;
                o.z = acc[i][2] + bv.z;
                o.w = acc[i][3] + bv.w;
                *reinterpret_cast<float4*>(&g_logits[0][0] + (size_t)r * VV + nc) = o;
            }
        } else {
#pragma unroll
            for (int i = 0; i < 8; i++) {
                int r = ty * 8 + i;
                float4 o;
                o.x = acc[i][0]; o.y = acc[i][1]; o.z = acc[i][2]; o.w = acc[i][3];
                *reinterpret_cast<float4*>(&g_lpart[0][0] + (size_t)r * VV + nc) = o;
            }
        }
    } else {
        float* P = &g_part[blockIdx.y][0][0];
#pragma unroll
        for (int i = 0; i < 8; i++) {
            int r = ty * 8 + i;
            float4 o;
            o.x = acc[i][0]; o.y = acc[i][1]; o.z = acc[i][2]; o.w = acc[i][3];
            *reinterpret_cast<float4*>(P + (size_t)r * 4096 + nc) = o;
        }
    }
}

// ---------------- LSTM cell: fused split-K reduce + bias/zb0 + cell ----------
__device__ __forceinline__ float sigf(float x) { return 1.f / (1.f + expf(-x)); }

__global__ void cell_kernel(int layer, const float* __restrict__ bias) {
    int idx4 = blockIdx.x * blockDim.x + threadIdx.x;
    if (idx4 >= RR * HH / 4) return;
    int r = idx4 >> 8;
    int j = (idx4 & 255) * 4;
    float* hA = layer ? &g_h1[0][0] : &g_h0[0][0];
    float* cA = layer ? &g_c1[0][0] : &g_c0[0][0];

    float4 gi, gf, gg, go;
    if (layer == 0) {
        const float* zb = &g_zb0[r & 31][0];
        gi = *reinterpret_cast<const float4*>(zb + j);
        gf = *reinterpret_cast<const float4*>(zb + j + HH);
        gg = *reinterpret_cast<const float4*>(zb + j + 2 * HH);
        go = *reinterpret_cast<const float4*>(zb + j + 3 * HH);
    } else {
        gi = *reinterpret_cast<const float4*>(bias + j);
        gf = *reinterpret_cast<const float4*>(bias + j + HH);
        gg = *reinterpret_cast<const float4*>(bias + j + 2 * HH);
        go = *reinterpret_cast<const float4*>(bias + j + 3 * HH);
    }
#pragma unroll
    for (int s = 0; s < NSPLIT; s++) {
        float4 a = *reinterpret_cast<const float4*>(&g_part[s][r][j]);
        float4 b = *reinterpret_cast<const float4*>(&g_part[s][r][j + HH]);
        float4 c = *reinterpret_cast<const float4*>(&g_part[s][r][j + 2 * HH]);
        float4 d = *reinterpret_cast<const float4*>(&g_part[s][r][j + 3 * HH]);
        gi.x += a.x; gi.y += a.y; gi.z += a.z; gi.w += a.w;
        gf.x += b.x; gf.y += b.y; gf.z += b.z; gf.w += b.w;
        gg.x += c.x; gg.y += c.y; gg.z += c.z; gg.w += c.w;
        go.x += d.x; go.y += d.y; go.z += d.z; go.w += d.w;
    }
    float4 cc = *reinterpret_cast<const float4*>(cA + (size_t)r * HH + j);
    float4 hh;
    cc.x = sigf(gf.x) * cc.x + sigf(gi.x) * tanhf(gg.x);
    cc.y = sigf(gf.y) * cc.y + sigf(gi.y) * tanhf(gg.y);
    cc.z = sigf(gf.z) * cc.z + sigf(gi.z) * tanhf(gg.z);
    cc.w = sigf(gf.w) * cc.w + sigf(gi.w) * tanhf(gg.w);
    hh.x = sigf(go.x) * tanhf(cc.x);
    hh.y = sigf(go.y) * tanhf(cc.y);
    hh.z = sigf(go.z) * tanhf(cc.z);
    hh.w = sigf(go.w) * tanhf(cc.w);
    *reinterpret_cast<float4*>(cA + (size_t)r * HH + j) = cc;
    *reinterpret_cast<float4*>(hA + (size_t)r * HH + j) = hh;
}

// ---------------- sampling phase 1: reduce split-K, chunk max/sum, chunk argmax --
// grid = RR*4 blocks (4 vocab chunks of 4000 per row), 256 threads.
// Chunk argmax uses score L + gumbel (argmax-invariant to m/lse).
__global__ __launch_bounds__(256) void sample1_kernel(
    uint32_t k0s0, uint32_t k1s0, uint32_t k0s1, uint32_t k1s1)
{
    const int r   = blockIdx.x >> 2;
    const int c   = blockIdx.x & 3;
    const int tid = threadIdx.x;
    const int stream = (r < BB) ? 0 : 1;
    const int b   = r & 31;
    float4* L4  = reinterpret_cast<float4*>(&g_logits[r][0]);
    const float4* P4 = reinterpret_cast<const float4*>(&g_lpart[r][0]);
    const int v40 = c * (VC / 4);           // 1000 float4 per chunk
    const int v41 = v40 + (VC / 4);

    __shared__ float red[256];
    __shared__ int   redi[256];

    // pass 1: reduce split-K in place + chunk max
    float m = -INFINITY;
    for (int v4 = v40 + tid; v4 < v41; v4 += 256) {
        float4 a = L4[v4];
        float4 p = P4[v4];
        a.x += p.x; a.y += p.y; a.z += p.z; a.w += p.w;
        L4[v4] = a;
        m = fmaxf(m, fmaxf(fmaxf(a.x, a.y), fmaxf(a.z, a.w)));
    }
    red[tid] = m; __syncthreads();
    for (int s = 128; s > 0; s >>= 1) {
        if (tid < s) red[tid] = fmaxf(red[tid], red[tid + s]);
        __syncthreads();
    }
    m = red[0]; __syncthreads();

    // pass 2: chunk sum of exp(L - m) + chunk argmax of (L + gumbel)
    const uint32_t k0 = stream ? k0s1 : k0s0;
    const uint32_t k1 = stream ? k1s1 : k1s0;
    float sum = 0.f;
    float best = -INFINITY; int bidx = VV;
    for (int v4 = v40 + tid; v4 < v41; v4 += 256) {
        float4 a = L4[v4];
        sum += expf(a.x - m) + expf(a.y - m) + expf(a.z - m) + expf(a.w - m);
        float lv[4] = {a.x, a.y, a.z, a.w};
#pragma unroll
        for (int e = 0; e < 4; e++) {
            int v = v4 * 4 + e;
            float g = jax_gumbel(k0, k1, (uint32_t)(b * VV + v));
            float sc = lv[e] + g;
            if (sc > best) { best = sc; bidx = v; }
        }
    }
    red[tid] = sum; __syncthreads();
    for (int s = 128; s > 0; s >>= 1) {
        if (tid < s) red[tid] += red[tid + s];
        __syncthreads();
    }
    float csum = red[0]; __syncthreads();

    red[tid] = best; redi[tid] = bidx; __syncthreads();
    for (int s = 128; s > 0; s >>= 1) {
        if (tid < s) {
            float o = red[tid + s]; int oi = redi[tid + s];
            if (o > red[tid] || (o == red[tid] && oi < redi[tid])) {
                red[tid] = o; redi[tid] = oi;
            }
        }
        __syncthreads();
    }
    if (tid == 0) {
        g_pm[r][c] = m;
        g_ps[r][c] = csum;
        g_pb[r][c] = red[0];
        g_pi[r][c] = redi[0];
    }
}

// ---------------- sampling phase 2: p write + argmax combine + token ------------
__global__ __launch_bounds__(256) void sample2_kernel(
    int t, const int* __restrict__ x, float* __restrict__ out)
{
    const int r   = blockIdx.x >> 2;
    const int c   = blockIdx.x & 3;
    const int tid = threadIdx.x;
    const int stream = (r < BB) ? 0 : 1;
    const int b   = r & 31;
    const float4* L4 = reinterpret_cast<const float4*>(&g_logits[r][0]);
    const int v40 = c * (VC / 4);
    const int v41 = v40 + (VC / 4);

    __shared__ float sh_mlse;

    if (tid == 0) {
        float m = fmaxf(fmaxf(g_pm[r][0], g_pm[r][1]), fmaxf(g_pm[r][2], g_pm[r][3]));
        float sum = g_ps[r][0] * expf(g_pm[r][0] - m)
                  + g_ps[r][1] * expf(g_pm[r][1] - m)
                  + g_ps[r][2] * expf(g_pm[r][2] - m)
                  + g_ps[r][3] * expf(g_pm[r][3] - m);
        sh_mlse = m + logf(sum);
    }
    __syncthreads();
    const float mlse = sh_mlse;

    const size_t p_off = stream ? ((size_t)4096 + (size_t)BB * TT * VV + 4096)
                                : (size_t)4096;
    const size_t pbase = p_off + ((size_t)b * TT + t) * VV;
    float4* O4 = reinterpret_cast<float4*>(out + pbase);

    for (int v4 = v40 + tid; v4 < v41; v4 += 256) {
        float4 a = L4[v4];
        float4 pw;
        pw.x = expf(a.x - mlse);
        pw.y = expf(a.y - mlse);
        pw.z = expf(a.z - mlse);
        pw.w = expf(a.w - mlse);
        O4[v4] = pw;
    }

    if (c == 0 && tid == 0) {
        float best = g_pb[r][0]; int bidx = g_pi[r][0];
#pragma unroll
        for (int q = 1; q < 4; q++) {
            float o = g_pb[r][q]; int oi = g_pi[r][q];
            if (o > best || (o == best && oi < bidx)) { best = o; bidx = oi; }
        }
        size_t sbase = stream ? ((size_t)4096 + (size_t)BB * TT * VV) : (size_t)0;
        out[sbase + (size_t)b * TT + t] = (float)bidx;
        g_tok[r] = stream ? x[(size_t)b * TT + t] : bidx;
    }
}

// ---------------- host driver ----------------
extern "C" void kernel_launch(void* const* d_in, const int* in_sizes, int n_in,
                              void* d_out, int out_size)
{
    const int*   x    = (const int*)  d_in[0];
    const float* z    = (const float*)d_in[1];
    const float* emb  = (const float*)d_in[2];
    const float* Wx0  = (const float*)d_in[3];
    const float* Wh0  = (const float*)d_in[4];
    const float* b0   = (const float*)d_in[5];
    const float* Wx1  = (const float*)d_in[6];
    const float* Wh1  = (const float*)d_in[7];
    const float* b1   = (const float*)d_in[8];
    const float* Wout = (const float*)d_in[9];
    const float* bout = (const float*)d_in[10];
    float* out = (float*)d_out;

    init_kernel<<<256, 256>>>();
    zb0_kernel<<<(BB * 4 * HH + 255) / 256, 256>>>(z, Wx0, b0);

    uint32_t s0a, s0b, s1a, s1b;
    h_fold(0u, 42u, 0u, &s0a, &s0b);
    h_fold(0u, 42u, 1u, &s1a, &s1b);

    for (int t = 0; t < TT; t++) {
        uint32_t k0s0, k1s0, k0s1, k1s1;
        h_fold(s0a, s0b, (uint32_t)t, &k0s0, &k1s0);
        h_fold(s1a, s1b, (uint32_t)t, &k0s1, &k1s1);

        gemm_kernel<0><<<dim3(32, NSPLIT), 256>>>(emb, Wx0, Wh0, b0);
        cell_kernel<<<(RR * HH / 4 + 255) / 256, 256>>>(0, b0);
        gemm_kernel<1><<<dim3(32, NSPLIT), 256>>>(emb, Wx1, Wh1, b1);
        cell_kernel<<<(RR * HH / 4 + 255) / 256, 256>>>(1, b1);
        gemm_kernel<2><<<dim3(125, 2), 256>>>(emb, Wout, Wout, bout);
        sample1_kernel<<<RR * 4, 256>>>(k0s0, k1s0, k0s1, k1s1);
        sample2_kernel<<<RR * 4, 256>>>(t, x, out);
    }
}